// round 1
// baseline (speedup 1.0000x reference)
#include <cuda_runtime.h>
#include <cuda_bf16.h>
#include <cstdint>

// Problem constants
#define LAYERS 6
#define BATCH  8
#define SEQ    1024
#define NTOK   (BATCH*SEQ)   // 8192
#define DMODEL 768
#define NHEAD  12
#define HDIM   64
#define D3     2304          // 3*DMODEL
#define DF     3072          // 4*DMODEL

// -------- scratch (device globals: no allocations allowed) --------
__device__ float g_x   [NTOK*DMODEL];   // activations
__device__ float g_qkv [NTOK*D3];       // qkv projections
__device__ float g_attn[NTOK*DMODEL];   // attention context
__device__ float g_proj[NTOK*DMODEL];   // proj / ffn2 output
__device__ float g_h   [NTOK*DF];       // ffn hidden
__device__ int   g_pos [NTOK];
__device__ int   g_pad [NTOK];

// ---------------- positions + pad mask ----------------
__global__ void pos_kernel(const int* __restrict__ tokens) {
    __shared__ int s[SEQ];
    int b = blockIdx.x, i = threadIdx.x;
    int t = tokens[b*SEQ + i];
    int isp = (t == 0);
    g_pad[b*SEQ + i] = isp;
    s[i] = 1 - isp;
    __syncthreads();
    for (int off = 1; off < SEQ; off <<= 1) {
        int v = (i >= off) ? s[i - off] : 0;
        __syncthreads();
        if (i >= off) s[i] += v;
        __syncthreads();
    }
    g_pos[b*SEQ + i] = isp ? 0 : s[i];
}

// ---------------- embedding ----------------
__global__ void embed_kernel(const int* __restrict__ tokens,
                             const float* __restrict__ tok_emb,
                             const float* __restrict__ pos_emb) {
    int n = blockIdx.x;
    int d = threadIdx.x * 4;          // 192 threads * 4 = 768
    int t = tokens[n];
    int p = g_pos[n];
    float4 a = *(const float4*)&tok_emb[(size_t)t*DMODEL + d];
    float4 c = *(const float4*)&pos_emb[(size_t)p*DMODEL + d];
    a.x += c.x; a.y += c.y; a.z += c.z; a.w += c.w;
    *(float4*)&g_x[(size_t)n*DMODEL + d] = a;
}

// ---------------- GELU ----------------
__device__ __forceinline__ float gelu_f(float x) {
    float x3 = x*x*x;
    return 0.5f*x*(1.f + tanhf(0.7978845608028654f*(x + 0.044715f*x3)));
}

// ---------------- GEMM: C[M,N] = A[M,K] * B[N,K]^T + bias, optional GELU ----------------
// 128x128 block tile, BK=16, 256 threads, 8x8 per thread.
template<bool GELU>
__global__ void __launch_bounds__(256) gemm_nt(const float* __restrict__ A,
                                               const float* __restrict__ B,
                                               const float* __restrict__ bias,
                                               float* __restrict__ C,
                                               int M, int N, int K) {
    __shared__ float As[16][128];
    __shared__ float Bs[16][128];
    int tid = threadIdx.x;
    int bm = blockIdx.y * 128, bn = blockIdx.x * 128;
    int tx = tid & 15, ty = tid >> 4;
    int lr = tid >> 2;              // 0..63
    int lc = (tid & 3) << 2;        // 0,4,8,12
    const float* Ab = A + (size_t)bm * K;
    const float* Bb = B + (size_t)bn * K;

    float acc[8][8];
#pragma unroll
    for (int i = 0; i < 8; i++)
#pragma unroll
        for (int j = 0; j < 8; j++) acc[i][j] = 0.f;

    for (int k0 = 0; k0 < K; k0 += 16) {
        float4 a0 = *(const float4*)&Ab[(size_t)lr*K        + k0 + lc];
        float4 a1 = *(const float4*)&Ab[(size_t)(lr+64)*K   + k0 + lc];
        float4 b0 = *(const float4*)&Bb[(size_t)lr*K        + k0 + lc];
        float4 b1 = *(const float4*)&Bb[(size_t)(lr+64)*K   + k0 + lc];
        __syncthreads();
        As[lc+0][lr]    = a0.x; As[lc+1][lr]    = a0.y; As[lc+2][lr]    = a0.z; As[lc+3][lr]    = a0.w;
        As[lc+0][lr+64] = a1.x; As[lc+1][lr+64] = a1.y; As[lc+2][lr+64] = a1.z; As[lc+3][lr+64] = a1.w;
        Bs[lc+0][lr]    = b0.x; Bs[lc+1][lr]    = b0.y; Bs[lc+2][lr]    = b0.z; Bs[lc+3][lr]    = b0.w;
        Bs[lc+0][lr+64] = b1.x; Bs[lc+1][lr+64] = b1.y; Bs[lc+2][lr+64] = b1.z; Bs[lc+3][lr+64] = b1.w;
        __syncthreads();
#pragma unroll
        for (int kk = 0; kk < 16; kk++) {
            float4 ar0 = *(const float4*)&As[kk][ty*8];
            float4 ar1 = *(const float4*)&As[kk][ty*8 + 4];
            float4 br0 = *(const float4*)&Bs[kk][tx*8];
            float4 br1 = *(const float4*)&Bs[kk][tx*8 + 4];
            float a[8] = {ar0.x, ar0.y, ar0.z, ar0.w, ar1.x, ar1.y, ar1.z, ar1.w};
            float b[8] = {br0.x, br0.y, br0.z, br0.w, br1.x, br1.y, br1.z, br1.w};
#pragma unroll
            for (int i = 0; i < 8; i++)
#pragma unroll
                for (int j = 0; j < 8; j++) acc[i][j] += a[i] * b[j];
        }
    }

    float bv[8];
#pragma unroll
    for (int j = 0; j < 8; j++) bv[j] = bias[bn + tx*8 + j];

#pragma unroll
    for (int i = 0; i < 8; i++) {
        float o[8];
#pragma unroll
        for (int j = 0; j < 8; j++) {
            float v = acc[i][j] + bv[j];
            if (GELU) v = gelu_f(v);
            o[j] = v;
        }
        size_t row = (size_t)(bm + ty*8 + i);
        float* Cp = &C[row * (size_t)N + bn + tx*8];
        *(float4*)&Cp[0] = make_float4(o[0], o[1], o[2], o[3]);
        *(float4*)&Cp[4] = make_float4(o[4], o[5], o[6], o[7]);
    }
}

// ---------------- attention (flash-style online softmax, causal skip) ----------------
// grid (64 qblocks, 12 heads, 8 batch), 256 threads. QB=16 query rows per block.
// Thread (qrow = tid/16, lane = tid%16): 4 scores per chunk, 4 output dims.
__global__ void __launch_bounds__(256) attn_kernel(const float* __restrict__ qkv,
                                                   float* __restrict__ out) {
    __shared__ float sQ [16*64];   // [q][k]
    __shared__ float sKT[64*64];   // [k][j]  (xor-swizzled)
    __shared__ float sV [64*64];   // [j][d]
    __shared__ float sP [16*64];   // probs chunk [q][j]

    int b = blockIdx.z, h = blockIdx.y, qb = blockIdx.x;
    int tid = threadIdx.x;
    int q0 = qb * 16;

    { // load Q tile (coalesced)
        int r = tid >> 4, c4 = (tid & 15) << 2;
        *(float4*)&sQ[r*64 + c4] =
            *(const float4*)&qkv[(size_t)(b*SEQ + q0 + r)*D3 + h*HDIM + c4];
    }

    int qrow = tid >> 4, lane = tid & 15;
    int qg = q0 + qrow;
    int dd = lane << 2;
    const int* padp = &g_pad[b*SEQ];

    float m_run = -1e30f, s_run = 0.f;
    float a0 = 0.f, a1 = 0.f, a2 = 0.f, a3 = 0.f;

    int nch = q0/64 + 1;    // causal: skip fully-masked kv chunks
    for (int c = 0; c < nch; c++) {
        __syncthreads();
        // load K chunk (transposed+swizzled) and V chunk (natural), coalesced
#pragma unroll
        for (int u = 0; u < 4; u++) {
            int idx = tid + u*256;          // 0..1023
            int r  = idx >> 4;              // 0..63 token within chunk
            int c4 = (idx & 15) << 2;       // 0..60
            const float* base = &qkv[(size_t)(b*SEQ + c*64 + r)*D3 + h*HDIM];
            *(float4*)&sV[r*64 + c4] = *(const float4*)(base + 2*DMODEL + c4);
            float4 kv = *(const float4*)(base + DMODEL + c4);
            sKT[(c4+0)*64 + (r ^ ((c4+0) & 60))] = kv.x;
            sKT[(c4+1)*64 + (r ^ ((c4+1) & 60))] = kv.y;
            sKT[(c4+2)*64 + (r ^ ((c4+2) & 60))] = kv.z;
            sKT[(c4+3)*64 + (r ^ ((c4+3) & 60))] = kv.w;
        }
        __syncthreads();

        // scores: 4 per thread
        float s0 = 0.f, s1 = 0.f, s2 = 0.f, s3 = 0.f;
#pragma unroll
        for (int k = 0; k < 64; k++) {
            float qv = sQ[qrow*64 + k];
            float4 kv = *(const float4*)&sKT[k*64 + ((lane*4) ^ (k & 60))];
            s0 += qv*kv.x; s1 += qv*kv.y; s2 += qv*kv.z; s3 += qv*kv.w;
        }
        int jb = c*64 + lane*4;
        float sc0 = (jb+0 > qg || padp[jb+0]) ? -1e9f : s0*0.125f;
        float sc1 = (jb+1 > qg || padp[jb+1]) ? -1e9f : s1*0.125f;
        float sc2 = (jb+2 > qg || padp[jb+2]) ? -1e9f : s2*0.125f;
        float sc3 = (jb+3 > qg || padp[jb+3]) ? -1e9f : s3*0.125f;

        // online softmax update (16-lane row group)
        float mc = fmaxf(fmaxf(sc0, sc1), fmaxf(sc2, sc3));
#pragma unroll
        for (int o = 8; o; o >>= 1) mc = fmaxf(mc, __shfl_xor_sync(0xffffffffu, mc, o, 16));
        float mn = fmaxf(m_run, mc);
        float alpha = expf(m_run - mn);
        float p0 = expf(sc0 - mn), p1 = expf(sc1 - mn), p2 = expf(sc2 - mn), p3 = expf(sc3 - mn);
        sP[qrow*64 + lane*4 + 0] = p0;
        sP[qrow*64 + lane*4 + 1] = p1;
        sP[qrow*64 + lane*4 + 2] = p2;
        sP[qrow*64 + lane*4 + 3] = p3;
        float ps = p0 + p1 + p2 + p3;
#pragma unroll
        for (int o = 8; o; o >>= 1) ps += __shfl_xor_sync(0xffffffffu, ps, o, 16);
        s_run = s_run * alpha + ps;
        m_run = mn;
        a0 *= alpha; a1 *= alpha; a2 *= alpha; a3 *= alpha;
        __syncthreads();

        // PV accumulate
#pragma unroll 8
        for (int j = 0; j < 64; j++) {
            float p = sP[qrow*64 + j];
            float4 vv = *(const float4*)&sV[j*64 + dd];
            a0 += p*vv.x; a1 += p*vv.y; a2 += p*vv.z; a3 += p*vv.w;
        }
    }

    // all-masked rows are zeroed (matches reference)
    float keep = (m_run > -1e8f) ? 1.f : 0.f;
    float inv = keep / s_run;
    float4 o = make_float4(a0*inv, a1*inv, a2*inv, a3*inv);
    *(float4*)&out[(size_t)(b*SEQ + qg)*DMODEL + h*HDIM + dd] = o;
}

// ---------------- layernorm(x + add) ----------------
__device__ __forceinline__ float block_sum(float v, float* sh) {
    int lane = threadIdx.x & 31, w = threadIdx.x >> 5;
#pragma unroll
    for (int o = 16; o; o >>= 1) v += __shfl_xor_sync(0xffffffffu, v, o);
    if (lane == 0) sh[w] = v;
    __syncthreads();
    float r = 0.f;
#pragma unroll
    for (int i = 0; i < 8; i++) r += sh[i];
    __syncthreads();
    return r;
}

__global__ void __launch_bounds__(256) ln_kernel(const float* __restrict__ xin,
                                                 const float* __restrict__ add,
                                                 const float* __restrict__ g,
                                                 const float* __restrict__ bta,
                                                 float* __restrict__ xout) {
    __shared__ float sh[8];
    int n = blockIdx.x, tid = threadIdx.x;
    float v[3];
    float s = 0.f;
#pragma unroll
    for (int i = 0; i < 3; i++) {
        int d = tid + i*256;
        v[i] = xin[(size_t)n*DMODEL + d] + add[(size_t)n*DMODEL + d];
        s += v[i];
    }
    s = block_sum(s, sh);
    float mu = s * (1.f/768.f);
    float q = 0.f;
#pragma unroll
    for (int i = 0; i < 3; i++) { float dv = v[i] - mu; q += dv*dv; }
    q = block_sum(q, sh);
    float rstd = rsqrtf(q * (1.f/768.f) + 1e-5f);
#pragma unroll
    for (int i = 0; i < 3; i++) {
        int d = tid + i*256;
        xout[(size_t)n*DMODEL + d] = (v[i] - mu) * rstd * g[d] + bta[d];
    }
}

// ---------------- output copy (x, then pad mask tail if present) ----------------
__global__ void copy_kernel(float* __restrict__ out, int out_size) {
    int idx = blockIdx.x*256 + threadIdx.x;
    if (idx >= out_size) return;
    const int NX = NTOK*DMODEL;
    if (idx < NX) {
        out[idx] = g_x[idx];
    } else {
        int pi = idx - NX;
        out[idx] = (pi < NTOK && g_pad[pi]) ? 1.f : 0.f;
    }
}

// ---------------- launcher ----------------
extern "C" void kernel_launch(void* const* d_in, const int* in_sizes, int n_in,
                              void* d_out, int out_size) {
    const int*   tokens  = (const int*)  d_in[0];
    const float* tok_emb = (const float*)d_in[1];
    const float* pos_emb = (const float*)d_in[2];
    const float* qkv_w   = (const float*)d_in[3];
    const float* qkv_b   = (const float*)d_in[4];
    const float* out_w   = (const float*)d_in[5];
    const float* out_b   = (const float*)d_in[6];
    const float* ln1_g   = (const float*)d_in[7];
    const float* ln1_b   = (const float*)d_in[8];
    const float* ff1_w   = (const float*)d_in[9];
    const float* ff1_b   = (const float*)d_in[10];
    const float* ff2_w   = (const float*)d_in[11];
    const float* ff2_b   = (const float*)d_in[12];
    const float* ln2_g   = (const float*)d_in[13];
    const float* ln2_b   = (const float*)d_in[14];
    float* out = (float*)d_out;

    float *px, *pqkv, *pattn, *pproj, *ph;
    cudaGetSymbolAddress((void**)&px,    g_x);
    cudaGetSymbolAddress((void**)&pqkv,  g_qkv);
    cudaGetSymbolAddress((void**)&pattn, g_attn);
    cudaGetSymbolAddress((void**)&pproj, g_proj);
    cudaGetSymbolAddress((void**)&ph,    g_h);

    pos_kernel<<<BATCH, SEQ>>>(tokens);
    embed_kernel<<<NTOK, DMODEL/4>>>(tokens, tok_emb, pos_emb);

    for (int l = 0; l < LAYERS; l++) {
        // QKV projection
        gemm_nt<false><<<dim3(D3/128, NTOK/128), 256>>>(
            px, qkv_w + (size_t)l*D3*DMODEL, qkv_b + (size_t)l*D3, pqkv,
            NTOK, D3, DMODEL);
        // attention
        attn_kernel<<<dim3(SEQ/16, NHEAD, BATCH), 256>>>(pqkv, pattn);
        // output projection
        gemm_nt<false><<<dim3(DMODEL/128, NTOK/128), 256>>>(
            pattn, out_w + (size_t)l*DMODEL*DMODEL, out_b + (size_t)l*DMODEL, pproj,
            NTOK, DMODEL, DMODEL);
        // x = LN(x + attn_out)
        ln_kernel<<<NTOK, 256>>>(px, pproj, ln1_g + (size_t)l*DMODEL, ln1_b + (size_t)l*DMODEL, px);
        // FFN
        gemm_nt<true><<<dim3(DF/128, NTOK/128), 256>>>(
            px, ff1_w + (size_t)l*DF*DMODEL, ff1_b + (size_t)l*DF, ph,
            NTOK, DF, DMODEL);
        gemm_nt<false><<<dim3(DMODEL/128, NTOK/128), 256>>>(
            ph, ff2_w + (size_t)l*DMODEL*DF, ff2_b + (size_t)l*DMODEL, pproj,
            NTOK, DMODEL, DF);
        // x = LN(x + ffn_out)
        ln_kernel<<<NTOK, 256>>>(px, pproj, ln2_g + (size_t)l*DMODEL, ln2_b + (size_t)l*DMODEL, px);
    }

    int nblk = (out_size + 255) / 256;
    if (nblk > 0) copy_kernel<<<nblk, 256>>>(out, out_size);
}

// round 2
// speedup vs baseline: 3.3742x; 3.3742x over previous
#include <cuda_runtime.h>
#include <cuda_bf16.h>
#include <cstdint>

// Problem constants
#define LAYERS 6
#define BATCH  8
#define SEQ    1024
#define NTOK   (BATCH*SEQ)   // 8192
#define DMODEL 768
#define NHEAD  12
#define HDIM   64
#define D3     2304          // 3*DMODEL
#define DF     3072          // 4*DMODEL

// -------- scratch (device globals: no allocations allowed) --------
__device__ float g_x   [NTOK*DMODEL];
__device__ float g_qkv [NTOK*D3];
__device__ float g_attn[NTOK*DMODEL];
__device__ float g_proj[NTOK*DMODEL];
__device__ float g_h   [NTOK*DF];
__device__ int   g_pos [NTOK];
__device__ int   g_pad [NTOK];

// ---------------- tf32 helpers ----------------
__device__ __forceinline__ uint32_t tf32u(float x) {
    uint32_t r;
    asm("cvt.rna.tf32.f32 %0, %1;" : "=r"(r) : "f"(x));
    return r;
}
__device__ __forceinline__ float tf32f(float x) { return __uint_as_float(tf32u(x)); }

__device__ __forceinline__ void mma8(float d[4],
                                     uint32_t a0, uint32_t a1, uint32_t a2, uint32_t a3,
                                     uint32_t b0, uint32_t b1) {
    asm volatile(
        "mma.sync.aligned.m16n8k8.row.col.f32.tf32.tf32.f32 "
        "{%0,%1,%2,%3}, {%4,%5,%6,%7}, {%8,%9}, {%0,%1,%2,%3};\n"
        : "+f"(d[0]), "+f"(d[1]), "+f"(d[2]), "+f"(d[3])
        : "r"(a0), "r"(a1), "r"(a2), "r"(a3), "r"(b0), "r"(b1));
}

// ---------------- positions + pad mask ----------------
__global__ void pos_kernel(const int* __restrict__ tokens) {
    __shared__ int s[SEQ];
    int b = blockIdx.x, i = threadIdx.x;
    int t = tokens[b*SEQ + i];
    int isp = (t == 0);
    g_pad[b*SEQ + i] = isp;
    s[i] = 1 - isp;
    __syncthreads();
    for (int off = 1; off < SEQ; off <<= 1) {
        int v = (i >= off) ? s[i - off] : 0;
        __syncthreads();
        if (i >= off) s[i] += v;
        __syncthreads();
    }
    g_pos[b*SEQ + i] = isp ? 0 : s[i];
}

// ---------------- embedding ----------------
__global__ void embed_kernel(const int* __restrict__ tokens,
                             const float* __restrict__ tok_emb,
                             const float* __restrict__ pos_emb) {
    int n = blockIdx.x;
    int d = threadIdx.x * 4;
    int t = tokens[n];
    int p = g_pos[n];
    float4 a = *(const float4*)&tok_emb[(size_t)t*DMODEL + d];
    float4 c = *(const float4*)&pos_emb[(size_t)p*DMODEL + d];
    a.x += c.x; a.y += c.y; a.z += c.z; a.w += c.w;
    *(float4*)&g_x[(size_t)n*DMODEL + d] = a;
}

// ---------------- GELU ----------------
__device__ __forceinline__ float gelu_f(float x) {
    float x3 = x*x*x;
    return 0.5f*x*(1.f + tanhf(0.7978845608028654f*(x + 0.044715f*x3)));
}

// ---------------- GEMM (tf32 tensor cores): C[M,N] = A[M,K]*B[N,K]^T + bias ----------------
// 128x128 block tile, BK=32, 256 threads = 8 warps in 2(m)x4(n) grid.
// Warp tile 64x32 = 4x4 m16n8k8 atoms. smem row pad 36 -> conflict-free frag LDS.
template<bool GELU>
__global__ void __launch_bounds__(256) gemm_tf32(const float* __restrict__ A,
                                                 const float* __restrict__ B,
                                                 const float* __restrict__ bias,
                                                 float* __restrict__ C,
                                                 int M, int N, int K) {
    __shared__ float As[128][36];
    __shared__ float Bs[128][36];
    int tid = threadIdx.x, warp = tid >> 5, lane = tid & 31;
    int g = lane >> 2, c = lane & 3;
    int wm = (warp & 1) * 64, wn = (warp >> 1) * 32;
    int bm = blockIdx.y * 128, bn = blockIdx.x * 128;

    float acc[4][4][4];
#pragma unroll
    for (int i = 0; i < 4; i++)
#pragma unroll
        for (int j = 0; j < 4; j++)
#pragma unroll
            for (int r = 0; r < 4; r++) acc[i][j][r] = 0.f;

    int lk = (tid & 7) << 2;   // k offset 0..28 step 4
    int lm = tid >> 3;         // row 0..31
    const float* Ap = A + (size_t)(bm + lm) * K + lk;
    const float* Bp = B + (size_t)(bn + lm) * K + lk;

    for (int k0 = 0; k0 < K; k0 += 32) {
        float4 av[4], bv[4];
#pragma unroll
        for (int i = 0; i < 4; i++) {
            av[i] = *(const float4*)(Ap + (size_t)(i*32)*K + k0);
            bv[i] = *(const float4*)(Bp + (size_t)(i*32)*K + k0);
        }
        __syncthreads();
#pragma unroll
        for (int i = 0; i < 4; i++) {
            float4 ta = make_float4(tf32f(av[i].x), tf32f(av[i].y), tf32f(av[i].z), tf32f(av[i].w));
            float4 tb = make_float4(tf32f(bv[i].x), tf32f(bv[i].y), tf32f(bv[i].z), tf32f(bv[i].w));
            *(float4*)&As[lm + i*32][lk] = ta;
            *(float4*)&Bs[lm + i*32][lk] = tb;
        }
        __syncthreads();
#pragma unroll
        for (int ks = 0; ks < 4; ks++) {
            uint32_t af[4][4], bf[4][2];
#pragma unroll
            for (int i = 0; i < 4; i++) {
                int r0 = wm + i*16 + g;
                af[i][0] = __float_as_uint(As[r0    ][ks*8 + c]);
                af[i][1] = __float_as_uint(As[r0 + 8][ks*8 + c]);
                af[i][2] = __float_as_uint(As[r0    ][ks*8 + c + 4]);
                af[i][3] = __float_as_uint(As[r0 + 8][ks*8 + c + 4]);
            }
#pragma unroll
            for (int j = 0; j < 4; j++) {
                int col = wn + j*8 + g;
                bf[j][0] = __float_as_uint(Bs[col][ks*8 + c]);
                bf[j][1] = __float_as_uint(Bs[col][ks*8 + c + 4]);
            }
#pragma unroll
            for (int i = 0; i < 4; i++)
#pragma unroll
                for (int j = 0; j < 4; j++)
                    mma8(acc[i][j], af[i][0], af[i][1], af[i][2], af[i][3], bf[j][0], bf[j][1]);
        }
    }

    // epilogue: bias (+gelu), float2 stores
#pragma unroll
    for (int j = 0; j < 4; j++) {
        int col0 = bn + wn + j*8 + c*2;
        float b0 = bias[col0], b1 = bias[col0 + 1];
#pragma unroll
        for (int i = 0; i < 4; i++) {
            int r0 = bm + wm + i*16 + g;
            float v00 = acc[i][j][0] + b0, v01 = acc[i][j][1] + b1;
            float v10 = acc[i][j][2] + b0, v11 = acc[i][j][3] + b1;
            if (GELU) { v00 = gelu_f(v00); v01 = gelu_f(v01); v10 = gelu_f(v10); v11 = gelu_f(v11); }
            *(float2*)&C[(size_t)r0 * N + col0]       = make_float2(v00, v01);
            *(float2*)&C[(size_t)(r0 + 8) * N + col0] = make_float2(v10, v11);
        }
    }
}

// ---------------- attention: flash-style with tf32 mma ----------------
// grid (16 qblocks of 64, 12 heads, 8 batch), 128 threads = 4 warps.
// Each warp owns 16 q rows. KV chunk = 64 keys. Q frags in registers (pre-scaled).
__global__ void __launch_bounds__(128) attn_mma(const float* __restrict__ qkv,
                                                float* __restrict__ out) {
    __shared__ float sK[64][68];   // [key][d]  pad 68 -> QK b-frag conflict-free
    __shared__ float sV[64][72];   // [key][d]  pad 72 -> PV b-frag conflict-free

    int b = blockIdx.z, h = blockIdx.y, qb = blockIdx.x;
    int tid = threadIdx.x, warp = tid >> 5, lane = tid & 31;
    int g = lane >> 2, c = lane & 3;
    int q0 = qb * 64;
    const int* padp = &g_pad[b*SEQ];

    // Q fragments (16 rows per warp), pre-scaled by 1/sqrt(64)
    uint32_t qa[8][4];
    int qg0 = q0 + warp*16 + g, qg1 = qg0 + 8;
    {
        const float* Q0 = qkv + (size_t)(b*SEQ + qg0) * D3 + h*HDIM;
        const float* Q1 = qkv + (size_t)(b*SEQ + qg1) * D3 + h*HDIM;
#pragma unroll
        for (int ks = 0; ks < 8; ks++) {
            qa[ks][0] = tf32u(Q0[ks*8 + c]     * 0.125f);
            qa[ks][1] = tf32u(Q1[ks*8 + c]     * 0.125f);
            qa[ks][2] = tf32u(Q0[ks*8 + c + 4] * 0.125f);
            qa[ks][3] = tf32u(Q1[ks*8 + c + 4] * 0.125f);
        }
    }

    float m0 = -1e30f, m1 = -1e30f, l0 = 0.f, l1 = 0.f;
    float o[8][4];
#pragma unroll
    for (int na = 0; na < 8; na++)
#pragma unroll
        for (int r = 0; r < 4; r++) o[na][r] = 0.f;

    int nch = q0/64 + 1;   // causal: later chunks fully masked
    for (int ch = 0; ch < nch; ch++) {
        __syncthreads();
        // load K,V chunk (coalesced float4, tf32-converted)
#pragma unroll
        for (int p = 0; p < 8; p++) {
            int idx = tid + p*128;
            int r = idx >> 4, q4 = (idx & 15) << 2;
            const float* base = qkv + (size_t)(b*SEQ + ch*64 + r) * D3 + h*HDIM;
            float4 kv = *(const float4*)(base + DMODEL   + q4);
            float4 vv = *(const float4*)(base + 2*DMODEL + q4);
            sK[r][q4+0] = tf32f(kv.x); sK[r][q4+1] = tf32f(kv.y);
            sK[r][q4+2] = tf32f(kv.z); sK[r][q4+3] = tf32f(kv.w);
            sV[r][q4+0] = tf32f(vv.x); sV[r][q4+1] = tf32f(vv.y);
            sV[r][q4+2] = tf32f(vv.z); sV[r][q4+3] = tf32f(vv.w);
        }
        __syncthreads();

        // S = Q K^T  (16 x 64 per warp)
        float s[8][4];
#pragma unroll
        for (int na = 0; na < 8; na++)
#pragma unroll
            for (int r = 0; r < 4; r++) s[na][r] = 0.f;
#pragma unroll
        for (int ks = 0; ks < 8; ks++) {
#pragma unroll
            for (int na = 0; na < 8; na++) {
                uint32_t b0 = __float_as_uint(sK[na*8 + g][ks*8 + c]);
                uint32_t b1 = __float_as_uint(sK[na*8 + g][ks*8 + c + 4]);
                mma8(s[na], qa[ks][0], qa[ks][1], qa[ks][2], qa[ks][3], b0, b1);
            }
        }

        // mask + online softmax. cols for regs {0,1}: na*8+c*2+{0,1}; rows qg0(regs0,1)/qg1(regs2,3)
        float mc0 = -1e30f, mc1 = -1e30f;
#pragma unroll
        for (int na = 0; na < 8; na++) {
            int j = ch*64 + na*8 + c*2;
            int p0 = padp[j], p1 = padp[j+1];
            float v00 = (j   > qg0 || p0) ? -1e9f : s[na][0];
            float v01 = (j+1 > qg0 || p1) ? -1e9f : s[na][1];
            float v10 = (j   > qg1 || p0) ? -1e9f : s[na][2];
            float v11 = (j+1 > qg1 || p1) ? -1e9f : s[na][3];
            s[na][0] = v00; s[na][1] = v01; s[na][2] = v10; s[na][3] = v11;
            mc0 = fmaxf(mc0, fmaxf(v00, v01));
            mc1 = fmaxf(mc1, fmaxf(v10, v11));
        }
        mc0 = fmaxf(mc0, __shfl_xor_sync(0xffffffffu, mc0, 1));
        mc0 = fmaxf(mc0, __shfl_xor_sync(0xffffffffu, mc0, 2));
        mc1 = fmaxf(mc1, __shfl_xor_sync(0xffffffffu, mc1, 1));
        mc1 = fmaxf(mc1, __shfl_xor_sync(0xffffffffu, mc1, 2));
        float mn0 = fmaxf(m0, mc0), mn1 = fmaxf(m1, mc1);
        float al0 = __expf(m0 - mn0), al1 = __expf(m1 - mn1);
        m0 = mn0; m1 = mn1;

        float ps0 = 0.f, ps1 = 0.f;
#pragma unroll
        for (int na = 0; na < 8; na++) {
            s[na][0] = __expf(s[na][0] - mn0);
            s[na][1] = __expf(s[na][1] - mn0);
            s[na][2] = __expf(s[na][2] - mn1);
            s[na][3] = __expf(s[na][3] - mn1);
            ps0 += s[na][0] + s[na][1];
            ps1 += s[na][2] + s[na][3];
        }
        ps0 += __shfl_xor_sync(0xffffffffu, ps0, 1);
        ps0 += __shfl_xor_sync(0xffffffffu, ps0, 2);
        ps1 += __shfl_xor_sync(0xffffffffu, ps1, 1);
        ps1 += __shfl_xor_sync(0xffffffffu, ps1, 2);
        l0 = l0 * al0 + ps0;
        l1 = l1 * al1 + ps1;
#pragma unroll
        for (int na = 0; na < 8; na++) {
            o[na][0] *= al0; o[na][1] *= al0;
            o[na][2] *= al1; o[na][3] *= al1;
        }

        // O += P V : A-frags for k-atom kk gathered from S via shuffles
        int srcA = (g << 2) + (c >> 1), srcB = srcA + 2;
        int sel = c & 1;
#pragma unroll
        for (int kk = 0; kk < 8; kk++) {
            float pa0 = __shfl_sync(0xffffffffu, s[kk][0], srcA);
            float pa1 = __shfl_sync(0xffffffffu, s[kk][1], srcA);
            float pa2 = __shfl_sync(0xffffffffu, s[kk][2], srcA);
            float pa3 = __shfl_sync(0xffffffffu, s[kk][3], srcA);
            float pb0 = __shfl_sync(0xffffffffu, s[kk][0], srcB);
            float pb1 = __shfl_sync(0xffffffffu, s[kk][1], srcB);
            float pb2 = __shfl_sync(0xffffffffu, s[kk][2], srcB);
            float pb3 = __shfl_sync(0xffffffffu, s[kk][3], srcB);
            uint32_t a0 = tf32u(sel ? pa1 : pa0);   // (row g,   k=c)
            uint32_t a1 = tf32u(sel ? pa3 : pa2);   // (row g+8, k=c)
            uint32_t a2 = tf32u(sel ? pb1 : pb0);   // (row g,   k=c+4)
            uint32_t a3 = tf32u(sel ? pb3 : pb2);   // (row g+8, k=c+4)
#pragma unroll
            for (int na = 0; na < 8; na++) {
                uint32_t b0 = __float_as_uint(sV[kk*8 + c    ][na*8 + g]);
                uint32_t b1 = __float_as_uint(sV[kk*8 + c + 4][na*8 + g]);
                mma8(o[na], a0, a1, a2, a3, b0, b1);
            }
        }
    }

    // normalize; all-masked rows -> 0 (matches reference)
    float inv0 = (m0 > -1e8f) ? 1.f / l0 : 0.f;
    float inv1 = (m1 > -1e8f) ? 1.f / l1 : 0.f;
    float* O0 = out + (size_t)(b*SEQ + qg0) * DMODEL + h*HDIM;
    float* O1 = out + (size_t)(b*SEQ + qg1) * DMODEL + h*HDIM;
#pragma unroll
    for (int na = 0; na < 8; na++) {
        int col = na*8 + c*2;
        *(float2*)&O0[col] = make_float2(o[na][0]*inv0, o[na][1]*inv0);
        *(float2*)&O1[col] = make_float2(o[na][2]*inv1, o[na][3]*inv1);
    }
}

// ---------------- layernorm(x + add) ----------------
__device__ __forceinline__ float block_sum(float v, float* sh) {
    int lane = threadIdx.x & 31, w = threadIdx.x >> 5;
#pragma unroll
    for (int o = 16; o; o >>= 1) v += __shfl_xor_sync(0xffffffffu, v, o);
    if (lane == 0) sh[w] = v;
    __syncthreads();
    float r = 0.f;
#pragma unroll
    for (int i = 0; i < 8; i++) r += sh[i];
    __syncthreads();
    return r;
}

__global__ void __launch_bounds__(256) ln_kernel(const float* __restrict__ xin,
                                                 const float* __restrict__ add,
                                                 const float* __restrict__ g,
                                                 const float* __restrict__ bta,
                                                 float* __restrict__ xout) {
    __shared__ float sh[8];
    int n = blockIdx.x, tid = threadIdx.x;
    float v[3];
    float s = 0.f;
#pragma unroll
    for (int i = 0; i < 3; i++) {
        int d = tid + i*256;
        v[i] = xin[(size_t)n*DMODEL + d] + add[(size_t)n*DMODEL + d];
        s += v[i];
    }
    s = block_sum(s, sh);
    float mu = s * (1.f/768.f);
    float q = 0.f;
#pragma unroll
    for (int i = 0; i < 3; i++) { float dv = v[i] - mu; q += dv*dv; }
    q = block_sum(q, sh);
    float rstd = rsqrtf(q * (1.f/768.f) + 1e-5f);
#pragma unroll
    for (int i = 0; i < 3; i++) {
        int d = tid + i*256;
        xout[(size_t)n*DMODEL + d] = (v[i] - mu) * rstd * g[d] + bta[d];
    }
}

// ---------------- output copy ----------------
__global__ void copy_kernel(float* __restrict__ out, int out_size) {
    int idx = blockIdx.x*256 + threadIdx.x;
    if (idx >= out_size) return;
    const int NX = NTOK*DMODEL;
    if (idx < NX) {
        out[idx] = g_x[idx];
    } else {
        int pi = idx - NX;
        out[idx] = (pi < NTOK && g_pad[pi]) ? 1.f : 0.f;
    }
}

// ---------------- launcher ----------------
extern "C" void kernel_launch(void* const* d_in, const int* in_sizes, int n_in,
                              void* d_out, int out_size) {
    const int*   tokens  = (const int*)  d_in[0];
    const float* tok_emb = (const float*)d_in[1];
    const float* pos_emb = (const float*)d_in[2];
    const float* qkv_w   = (const float*)d_in[3];
    const float* qkv_b   = (const float*)d_in[4];
    const float* out_w   = (const float*)d_in[5];
    const float* out_b   = (const float*)d_in[6];
    const float* ln1_g   = (const float*)d_in[7];
    const float* ln1_b   = (const float*)d_in[8];
    const float* ff1_w   = (const float*)d_in[9];
    const float* ff1_b   = (const float*)d_in[10];
    const float* ff2_w   = (const float*)d_in[11];
    const float* ff2_b   = (const float*)d_in[12];
    const float* ln2_g   = (const float*)d_in[13];
    const float* ln2_b   = (const float*)d_in[14];
    float* out = (float*)d_out;

    float *px, *pqkv, *pattn, *pproj, *ph;
    cudaGetSymbolAddress((void**)&px,    g_x);
    cudaGetSymbolAddress((void**)&pqkv,  g_qkv);
    cudaGetSymbolAddress((void**)&pattn, g_attn);
    cudaGetSymbolAddress((void**)&pproj, g_proj);
    cudaGetSymbolAddress((void**)&ph,    g_h);

    pos_kernel<<<BATCH, SEQ>>>(tokens);
    embed_kernel<<<NTOK, DMODEL/4>>>(tokens, tok_emb, pos_emb);

    for (int l = 0; l < LAYERS; l++) {
        gemm_tf32<false><<<dim3(D3/128, NTOK/128), 256>>>(
            px, qkv_w + (size_t)l*D3*DMODEL, qkv_b + (size_t)l*D3, pqkv,
            NTOK, D3, DMODEL);
        attn_mma<<<dim3(SEQ/64, NHEAD, BATCH), 128>>>(pqkv, pattn);
        gemm_tf32<false><<<dim3(DMODEL/128, NTOK/128), 256>>>(
            pattn, out_w + (size_t)l*DMODEL*DMODEL, out_b + (size_t)l*DMODEL, pproj,
            NTOK, DMODEL, DMODEL);
        ln_kernel<<<NTOK, 256>>>(px, pproj, ln1_g + (size_t)l*DMODEL, ln1_b + (size_t)l*DMODEL, px);
        gemm_tf32<true><<<dim3(DF/128, NTOK/128), 256>>>(
            px, ff1_w + (size_t)l*DF*DMODEL, ff1_b + (size_t)l*DF, ph,
            NTOK, DF, DMODEL);
        gemm_tf32<false><<<dim3(DMODEL/128, NTOK/128), 256>>>(
            ph, ff2_w + (size_t)l*DMODEL*DF, ff2_b + (size_t)l*DMODEL, pproj,
            NTOK, DMODEL, DF);
        ln_kernel<<<NTOK, 256>>>(px, pproj, ln2_g + (size_t)l*DMODEL, ln2_b + (size_t)l*DMODEL, px);
    }

    int nblk = (out_size + 255) / 256;
    if (nblk > 0) copy_kernel<<<nblk, 256>>>(out, out_size);
}

// round 4
// speedup vs baseline: 4.0700x; 1.2062x over previous
#include <cuda_runtime.h>
#include <cuda_bf16.h>
#include <cstdint>

// Problem constants
#define LAYERS 6
#define BATCH  8
#define SEQ    1024
#define NTOK   (BATCH*SEQ)   // 8192
#define DMODEL 768
#define NHEAD  12
#define HDIM   64
#define D3     2304          // 3*DMODEL
#define DF     3072          // 4*DMODEL

#define DD     (DMODEL*DMODEL)
// pre-rounded weight scratch layout
#define OFF_QKV 0
#define OFF_OUT (LAYERS*3*DD)
#define OFF_FF1 (OFF_OUT + LAYERS*DD)
#define OFF_FF2 (OFF_FF1 + LAYERS*4*DD)
#define WTOTAL  (OFF_FF2 + LAYERS*4*DD)   // 6*12*DD = 42,467,328 floats

// -------- scratch (device globals: no allocations allowed) --------
__device__ float g_x   [NTOK*DMODEL];   // exact activations (residual path)
__device__ float g_xr  [NTOK*DMODEL];   // tf32-rounded copy (GEMM A input)
__device__ float g_qkv [NTOK*D3];
__device__ float g_attn[NTOK*DMODEL];
__device__ float g_proj[NTOK*DMODEL];
__device__ float g_h   [NTOK*DF];
__device__ float g_wts [WTOTAL];        // tf32-rounded weights
__device__ int   g_pos [NTOK];
__device__ int   g_pad [NTOK];

// ---------------- helpers ----------------
__device__ __forceinline__ uint32_t tf32u(float x) {
    uint32_t r;
    asm("cvt.rna.tf32.f32 %0, %1;" : "=r"(r) : "f"(x));
    return r;
}
__device__ __forceinline__ float tf32f(float x) { return __uint_as_float(tf32u(x)); }

__device__ __forceinline__ uint32_t smem_u32(const void* p) {
    uint32_t a;
    asm("{ .reg .u64 t; cvta.to.shared.u64 t, %1; cvt.u32.u64 %0, t; }" : "=r"(a) : "l"(p));
    return a;
}

__device__ __forceinline__ void cp16(uint32_t dst, const void* src) {
    asm volatile("cp.async.cg.shared.global [%0], [%1], 16;" :: "r"(dst), "l"(src));
}
#define CP_COMMIT() asm volatile("cp.async.commit_group;" ::: "memory")
#define CP_WAIT(n)  asm volatile("cp.async.wait_group %0;" :: "n"(n) : "memory")

__device__ __forceinline__ void mma8(float d[4],
                                     uint32_t a0, uint32_t a1, uint32_t a2, uint32_t a3,
                                     uint32_t b0, uint32_t b1) {
    asm volatile(
        "mma.sync.aligned.m16n8k8.row.col.f32.tf32.tf32.f32 "
        "{%0,%1,%2,%3}, {%4,%5,%6,%7}, {%8,%9}, {%0,%1,%2,%3};\n"
        : "+f"(d[0]), "+f"(d[1]), "+f"(d[2]), "+f"(d[3])
        : "r"(a0), "r"(a1), "r"(a2), "r"(a3), "r"(b0), "r"(b1));
}

// ---------------- one-time weight rounding ----------------
__global__ void round_copy(const float* __restrict__ src, float* __restrict__ dst, int n4) {
    int i = blockIdx.x*256 + threadIdx.x;
    if (i >= n4) return;
    float4 v = ((const float4*)src)[i];
    v.x = tf32f(v.x); v.y = tf32f(v.y); v.z = tf32f(v.z); v.w = tf32f(v.w);
    ((float4*)dst)[i] = v;
}

// ---------------- positions + pad mask ----------------
__global__ void pos_kernel(const int* __restrict__ tokens) {
    __shared__ int s[SEQ];
    int b = blockIdx.x, i = threadIdx.x;
    int t = tokens[b*SEQ + i];
    int isp = (t == 0);
    g_pad[b*SEQ + i] = isp;
    s[i] = 1 - isp;
    __syncthreads();
    for (int off = 1; off < SEQ; off <<= 1) {
        int v = (i >= off) ? s[i - off] : 0;
        __syncthreads();
        if (i >= off) s[i] += v;
        __syncthreads();
    }
    g_pos[b*SEQ + i] = isp ? 0 : s[i];
}

// ---------------- embedding (writes exact + rounded) ----------------
__global__ void embed_kernel(const int* __restrict__ tokens,
                             const float* __restrict__ tok_emb,
                             const float* __restrict__ pos_emb) {
    int n = blockIdx.x;
    int d = threadIdx.x * 4;
    int t = tokens[n];
    int p = g_pos[n];
    float4 a = *(const float4*)&tok_emb[(size_t)t*DMODEL + d];
    float4 c = *(const float4*)&pos_emb[(size_t)p*DMODEL + d];
    a.x += c.x; a.y += c.y; a.z += c.z; a.w += c.w;
    *(float4*)&g_x[(size_t)n*DMODEL + d] = a;
    float4 r = make_float4(tf32f(a.x), tf32f(a.y), tf32f(a.z), tf32f(a.w));
    *(float4*)&g_xr[(size_t)n*DMODEL + d] = r;
}

// ---------------- GELU ----------------
__device__ __forceinline__ float gelu_f(float x) {
    float x3 = x*x*x;
    return 0.5f*x*(1.f + tanhf(0.7978845608028654f*(x + 0.044715f*x3)));
}

// ================= GEMM v2: tf32 mma.sync + cp.async double buffer =================
// C[M,N] = A[M,K]*B[N,K]^T + bias. 128x128x32 tile, 256 thr = 8 warps (2m x 4n),
// warp tile 64x32 = 4x4 m16n8k8. Inputs pre-rounded to tf32. Optional GELU, optional
// tf32-rounded store (when C feeds another GEMM as A).
#define G2_STAGE (128*36)                 // floats per operand per stage
#define G2_SMEM  (4*G2_STAGE*4)           // bytes: A0,A1,B0,B1 = 73728

template<bool GELU, bool ROUND>
__global__ void __launch_bounds__(256) gemm2(const float* __restrict__ A,
                                             const float* __restrict__ B,
                                             const float* __restrict__ bias,
                                             float* __restrict__ C,
                                             int M, int N, int K) {
    extern __shared__ float sm[];
    float* As = sm;                  // [2][128][36]
    float* Bs = sm + 2*G2_STAGE;     // [2][128][36]
    uint32_t aAddr = smem_u32(As), bAddr = smem_u32(Bs);

    int tid = threadIdx.x, warp = tid >> 5, lane = tid & 31;
    int g = lane >> 2, c = lane & 3;
    int wm = (warp & 1) * 64, wn = (warp >> 1) * 32;
    int bm = blockIdx.y * 128, bn = blockIdx.x * 128;

    const float* Ag = A + (size_t)bm * K;
    const float* Bg = B + (size_t)bn * K;
    int nkt = K >> 5;

    // per-thread copy geometry: 4 chunks of 16B per operand per stage
    int r0 = tid >> 1;                 // used as ci>>3 pattern below
    (void)r0;

    float acc[4][4][4];
#pragma unroll
    for (int i = 0; i < 4; i++)
#pragma unroll
        for (int j = 0; j < 4; j++)
#pragma unroll
            for (int r = 0; r < 4; r++) acc[i][j][r] = 0.f;

    auto issue = [&](int kt) {
        int st = kt & 1;
        int k0 = kt << 5;
        uint32_t aBase = aAddr + st * (G2_STAGE*4);
        uint32_t bBase = bAddr + st * (G2_STAGE*4);
#pragma unroll
        for (int p = 0; p < 4; p++) {
            int ci = p*256 + tid;
            int r = ci >> 3, kc = ci & 7;
            cp16(aBase + (uint32_t)(r*144 + kc*16), Ag + (size_t)r*K + k0 + kc*4);
            cp16(bBase + (uint32_t)(r*144 + kc*16), Bg + (size_t)r*K + k0 + kc*4);
        }
        CP_COMMIT();
    };

    issue(0);
    for (int kt = 0; kt < nkt; kt++) {
        int st = kt & 1;
        if (kt + 1 < nkt) { issue(kt + 1); CP_WAIT(1); }
        else              { CP_WAIT(0); }
        __syncthreads();

        const float* Ast = As + st*G2_STAGE;
        const float* Bst = Bs + st*G2_STAGE;
#pragma unroll
        for (int ks = 0; ks < 4; ks++) {
            uint32_t af[4][4], bf[4][2];
#pragma unroll
            for (int i = 0; i < 4; i++) {
                int rr = wm + i*16 + g;
                af[i][0] = __float_as_uint(Ast[rr*36       + ks*8 + c]);
                af[i][1] = __float_as_uint(Ast[(rr+8)*36   + ks*8 + c]);
                af[i][2] = __float_as_uint(Ast[rr*36       + ks*8 + c + 4]);
                af[i][3] = __float_as_uint(Ast[(rr+8)*36   + ks*8 + c + 4]);
            }
#pragma unroll
            for (int j = 0; j < 4; j++) {
                int col = wn + j*8 + g;
                bf[j][0] = __float_as_uint(Bst[col*36 + ks*8 + c]);
                bf[j][1] = __float_as_uint(Bst[col*36 + ks*8 + c + 4]);
            }
#pragma unroll
            for (int i = 0; i < 4; i++)
#pragma unroll
                for (int j = 0; j < 4; j++)
                    mma8(acc[i][j], af[i][0], af[i][1], af[i][2], af[i][3], bf[j][0], bf[j][1]);
        }
        __syncthreads();
    }

    // epilogue
#pragma unroll
    for (int j = 0; j < 4; j++) {
        int col0 = bn + wn + j*8 + c*2;
        float b0 = bias[col0], b1 = bias[col0 + 1];
#pragma unroll
        for (int i = 0; i < 4; i++) {
            int rr = bm + wm + i*16 + g;
            float v00 = acc[i][j][0] + b0, v01 = acc[i][j][1] + b1;
            float v10 = acc[i][j][2] + b0, v11 = acc[i][j][3] + b1;
            if (GELU)  { v00 = gelu_f(v00); v01 = gelu_f(v01); v10 = gelu_f(v10); v11 = gelu_f(v11); }
            if (ROUND) { v00 = tf32f(v00);  v01 = tf32f(v01);  v10 = tf32f(v10);  v11 = tf32f(v11); }
            *(float2*)&C[(size_t)rr * N + col0]       = make_float2(v00, v01);
            *(float2*)&C[(size_t)(rr + 8) * N + col0] = make_float2(v10, v11);
        }
    }
}

// ---------------- attention: flash-style with tf32 mma ----------------
__global__ void __launch_bounds__(128) attn_mma(const float* __restrict__ qkv,
                                                float* __restrict__ out) {
    __shared__ float sK[64][68];
    __shared__ float sV[64][72];

    int b = blockIdx.z, h = blockIdx.y, qb = blockIdx.x;
    int tid = threadIdx.x, warp = tid >> 5, lane = tid & 31;
    int g = lane >> 2, c = lane & 3;
    int q0 = qb * 64;
    const int* padp = &g_pad[b*SEQ];

    uint32_t qa[8][4];
    int qg0 = q0 + warp*16 + g, qg1 = qg0 + 8;
    {
        const float* Q0 = qkv + (size_t)(b*SEQ + qg0) * D3 + h*HDIM;
        const float* Q1 = qkv + (size_t)(b*SEQ + qg1) * D3 + h*HDIM;
#pragma unroll
        for (int ks = 0; ks < 8; ks++) {
            qa[ks][0] = tf32u(Q0[ks*8 + c]     * 0.125f);
            qa[ks][1] = tf32u(Q1[ks*8 + c]     * 0.125f);
            qa[ks][2] = tf32u(Q0[ks*8 + c + 4] * 0.125f);
            qa[ks][3] = tf32u(Q1[ks*8 + c + 4] * 0.125f);
        }
    }

    float m0 = -1e30f, m1 = -1e30f, l0 = 0.f, l1 = 0.f;
    float o[8][4];
#pragma unroll
    for (int na = 0; na < 8; na++)
#pragma unroll
        for (int r = 0; r < 4; r++) o[na][r] = 0.f;

    int nch = q0/64 + 1;
    for (int ch = 0; ch < nch; ch++) {
        __syncthreads();
#pragma unroll
        for (int p = 0; p < 8; p++) {
            int idx = tid + p*128;
            int r = idx >> 4, q4 = (idx & 15) << 2;
            const float* base = qkv + (size_t)(b*SEQ + ch*64 + r) * D3 + h*HDIM;
            float4 kv = *(const float4*)(base + DMODEL   + q4);
            float4 vv = *(const float4*)(base + 2*DMODEL + q4);
            sK[r][q4+0] = kv.x; sK[r][q4+1] = kv.y;
            sK[r][q4+2] = kv.z; sK[r][q4+3] = kv.w;
            sV[r][q4+0] = vv.x; sV[r][q4+1] = vv.y;
            sV[r][q4+2] = vv.z; sV[r][q4+3] = vv.w;
        }
        __syncthreads();

        float s[8][4];
#pragma unroll
        for (int na = 0; na < 8; na++)
#pragma unroll
            for (int r = 0; r < 4; r++) s[na][r] = 0.f;
#pragma unroll
        for (int ks = 0; ks < 8; ks++) {
#pragma unroll
            for (int na = 0; na < 8; na++) {
                uint32_t b0 = __float_as_uint(sK[na*8 + g][ks*8 + c]);
                uint32_t b1 = __float_as_uint(sK[na*8 + g][ks*8 + c + 4]);
                mma8(s[na], qa[ks][0], qa[ks][1], qa[ks][2], qa[ks][3], b0, b1);
            }
        }

        float mc0 = -1e30f, mc1 = -1e30f;
#pragma unroll
        for (int na = 0; na < 8; na++) {
            int j = ch*64 + na*8 + c*2;
            int p0 = padp[j], p1 = padp[j+1];
            float v00 = (j   > qg0 || p0) ? -1e9f : s[na][0];
            float v01 = (j+1 > qg0 || p1) ? -1e9f : s[na][1];
            float v10 = (j   > qg1 || p0) ? -1e9f : s[na][2];
            float v11 = (j+1 > qg1 || p1) ? -1e9f : s[na][3];
            s[na][0] = v00; s[na][1] = v01; s[na][2] = v10; s[na][3] = v11;
            mc0 = fmaxf(mc0, fmaxf(v00, v01));
            mc1 = fmaxf(mc1, fmaxf(v10, v11));
        }
        mc0 = fmaxf(mc0, __shfl_xor_sync(0xffffffffu, mc0, 1));
        mc0 = fmaxf(mc0, __shfl_xor_sync(0xffffffffu, mc0, 2));
        mc1 = fmaxf(mc1, __shfl_xor_sync(0xffffffffu, mc1, 1));
        mc1 = fmaxf(mc1, __shfl_xor_sync(0xffffffffu, mc1, 2));
        float mn0 = fmaxf(m0, mc0), mn1 = fmaxf(m1, mc1);
        float al0 = __expf(m0 - mn0), al1 = __expf(m1 - mn1);
        m0 = mn0; m1 = mn1;

        float ps0 = 0.f, ps1 = 0.f;
#pragma unroll
        for (int na = 0; na < 8; na++) {
            s[na][0] = __expf(s[na][0] - mn0);
            s[na][1] = __expf(s[na][1] - mn0);
            s[na][2] = __expf(s[na][2] - mn1);
            s[na][3] = __expf(s[na][3] - mn1);
            ps0 += s[na][0] + s[na][1];
            ps1 += s[na][2] + s[na][3];
        }
        ps0 += __shfl_xor_sync(0xffffffffu, ps0, 1);
        ps0 += __shfl_xor_sync(0xffffffffu, ps0, 2);
        ps1 += __shfl_xor_sync(0xffffffffu, ps1, 1);
        ps1 += __shfl_xor_sync(0xffffffffu, ps1, 2);
        l0 = l0 * al0 + ps0;
        l1 = l1 * al1 + ps1;
#pragma unroll
        for (int na = 0; na < 8; na++) {
            o[na][0] *= al0; o[na][1] *= al0;
            o[na][2] *= al1; o[na][3] *= al1;
        }

        int srcA = (g << 2) + (c >> 1), srcB = srcA + 2;
        int sel = c & 1;
#pragma unroll
        for (int kk = 0; kk < 8; kk++) {
            float pa0 = __shfl_sync(0xffffffffu, s[kk][0], srcA);
            float pa1 = __shfl_sync(0xffffffffu, s[kk][1], srcA);
            float pa2 = __shfl_sync(0xffffffffu, s[kk][2], srcA);
            float pa3 = __shfl_sync(0xffffffffu, s[kk][3], srcA);
            float pb0 = __shfl_sync(0xffffffffu, s[kk][0], srcB);
            float pb1 = __shfl_sync(0xffffffffu, s[kk][1], srcB);
            float pb2 = __shfl_sync(0xffffffffu, s[kk][2], srcB);
            float pb3 = __shfl_sync(0xffffffffu, s[kk][3], srcB);
            uint32_t a0 = tf32u(sel ? pa1 : pa0);
            uint32_t a1 = tf32u(sel ? pa3 : pa2);
            uint32_t a2 = tf32u(sel ? pb1 : pb0);
            uint32_t a3 = tf32u(sel ? pb3 : pb2);
#pragma unroll
            for (int na = 0; na < 8; na++) {
                uint32_t b0 = __float_as_uint(sV[kk*8 + c    ][na*8 + g]);
                uint32_t b1 = __float_as_uint(sV[kk*8 + c + 4][na*8 + g]);
                mma8(o[na], a0, a1, a2, a3, b0, b1);
            }
        }
    }

    // normalize, round to tf32 (feeds out-proj GEMM as A)
    float inv0 = (m0 > -1e8f) ? 1.f / l0 : 0.f;
    float inv1 = (m1 > -1e8f) ? 1.f / l1 : 0.f;
    float* O0 = out + (size_t)(b*SEQ + qg0) * DMODEL + h*HDIM;
    float* O1 = out + (size_t)(b*SEQ + qg1) * DMODEL + h*HDIM;
#pragma unroll
    for (int na = 0; na < 8; na++) {
        int col = na*8 + c*2;
        *(float2*)&O0[col] = make_float2(tf32f(o[na][0]*inv0), tf32f(o[na][1]*inv0));
        *(float2*)&O1[col] = make_float2(tf32f(o[na][2]*inv1), tf32f(o[na][3]*inv1));
    }
}

// ---------------- layernorm(x + add), writes exact + rounded ----------------
__device__ __forceinline__ float block_sum(float v, float* sh) {
    int lane = threadIdx.x & 31, w = threadIdx.x >> 5;
#pragma unroll
    for (int o = 16; o; o >>= 1) v += __shfl_xor_sync(0xffffffffu, v, o);
    if (lane == 0) sh[w] = v;
    __syncthreads();
    float r = 0.f;
#pragma unroll
    for (int i = 0; i < 8; i++) r += sh[i];
    __syncthreads();
    return r;
}

__global__ void __launch_bounds__(256) ln_kernel(const float* __restrict__ xin,
                                                 const float* __restrict__ add,
                                                 const float* __restrict__ g,
                                                 const float* __restrict__ bta,
                                                 float* __restrict__ xout,
                                                 float* __restrict__ xoutR) {
    __shared__ float sh[8];
    int n = blockIdx.x, tid = threadIdx.x;
    float v[3];
    float s = 0.f;
#pragma unroll
    for (int i = 0; i < 3; i++) {
        int d = tid + i*256;
        v[i] = xin[(size_t)n*DMODEL + d] + add[(size_t)n*DMODEL + d];
        s += v[i];
    }
    s = block_sum(s, sh);
    float mu = s * (1.f/768.f);
    float q = 0.f;
#pragma unroll
    for (int i = 0; i < 3; i++) { float dv = v[i] - mu; q += dv*dv; }
    q = block_sum(q, sh);
    float rstd = rsqrtf(q * (1.f/768.f) + 1e-5f);
#pragma unroll
    for (int i = 0; i < 3; i++) {
        int d = tid + i*256;
        float o = (v[i] - mu) * rstd * g[d] + bta[d];
        xout [(size_t)n*DMODEL + d] = o;
        xoutR[(size_t)n*DMODEL + d] = tf32f(o);
    }
}

// ---------------- output copy ----------------
__global__ void copy_kernel(float* __restrict__ out, int out_size) {
    int idx = blockIdx.x*256 + threadIdx.x;
    if (idx >= out_size) return;
    const int NX = NTOK*DMODEL;
    if (idx < NX) {
        out[idx] = g_x[idx];
    } else {
        int pi = idx - NX;
        out[idx] = (pi < NTOK && g_pad[pi]) ? 1.f : 0.f;
    }
}

// ---------------- launcher ----------------
extern "C" void kernel_launch(void* const* d_in, const int* in_sizes, int n_in,
                              void* d_out, int out_size) {
    const int*   tokens  = (const int*)  d_in[0];
    const float* tok_emb = (const float*)d_in[1];
    const float* pos_emb = (const float*)d_in[2];
    const float* qkv_w   = (const float*)d_in[3];
    const float* qkv_b   = (const float*)d_in[4];
    const float* out_w   = (const float*)d_in[5];
    const float* out_b   = (const float*)d_in[6];
    const float* ln1_g   = (const float*)d_in[7];
    const float* ln1_b   = (const float*)d_in[8];
    const float* ff1_w   = (const float*)d_in[9];
    const float* ff1_b   = (const float*)d_in[10];
    const float* ff2_w   = (const float*)d_in[11];
    const float* ff2_b   = (const float*)d_in[12];
    const float* ln2_g   = (const float*)d_in[13];
    const float* ln2_b   = (const float*)d_in[14];
    float* out = (float*)d_out;

    float *px, *pxr, *pqkv, *pattn, *pproj, *ph, *pw;
    cudaGetSymbolAddress((void**)&px,    g_x);
    cudaGetSymbolAddress((void**)&pxr,   g_xr);
    cudaGetSymbolAddress((void**)&pqkv,  g_qkv);
    cudaGetSymbolAddress((void**)&pattn, g_attn);
    cudaGetSymbolAddress((void**)&pproj, g_proj);
    cudaGetSymbolAddress((void**)&ph,    g_h);
    cudaGetSymbolAddress((void**)&pw,    g_wts);

    cudaFuncSetAttribute(gemm2<false,false>, cudaFuncAttributeMaxDynamicSharedMemorySize, G2_SMEM);
    cudaFuncSetAttribute(gemm2<false,true>,  cudaFuncAttributeMaxDynamicSharedMemorySize, G2_SMEM);
    cudaFuncSetAttribute(gemm2<true,true>,   cudaFuncAttributeMaxDynamicSharedMemorySize, G2_SMEM);

    // one-time weight rounding into scratch
    round_copy<<<(LAYERS*3*DD/4 + 255)/256, 256>>>(qkv_w, pw + OFF_QKV, LAYERS*3*DD/4);
    round_copy<<<(LAYERS*DD/4   + 255)/256, 256>>>(out_w, pw + OFF_OUT, LAYERS*DD/4);
    round_copy<<<(LAYERS*4*DD/4 + 255)/256, 256>>>(ff1_w, pw + OFF_FF1, LAYERS*4*DD/4);
    round_copy<<<(LAYERS*4*DD/4 + 255)/256, 256>>>(ff2_w, pw + OFF_FF2, LAYERS*4*DD/4);

    pos_kernel<<<BATCH, SEQ>>>(tokens);
    embed_kernel<<<NTOK, DMODEL/4>>>(tokens, tok_emb, pos_emb);

    for (int l = 0; l < LAYERS; l++) {
        gemm2<false,true><<<dim3(D3/128, NTOK/128), 256, G2_SMEM>>>(
            pxr, pw + OFF_QKV + (size_t)l*3*DD, qkv_b + (size_t)l*D3, pqkv,
            NTOK, D3, DMODEL);
        attn_mma<<<dim3(SEQ/64, NHEAD, BATCH), 128>>>(pqkv, pattn);
        gemm2<false,false><<<dim3(DMODEL/128, NTOK/128), 256, G2_SMEM>>>(
            pattn, pw + OFF_OUT + (size_t)l*DD, out_b + (size_t)l*DMODEL, pproj,
            NTOK, DMODEL, DMODEL);
        ln_kernel<<<NTOK, 256>>>(px, pproj, ln1_g + (size_t)l*DMODEL, ln1_b + (size_t)l*DMODEL, px, pxr);
        gemm2<true,true><<<dim3(DF/128, NTOK/128), 256, G2_SMEM>>>(
            pxr, pw + OFF_FF1 + (size_t)l*4*DD, ff1_b + (size_t)l*DF, ph,
            NTOK, DF, DMODEL);
        gemm2<false,false><<<dim3(DMODEL/128, NTOK/128), 256, G2_SMEM>>>(
            ph, pw + OFF_FF2 + (size_t)l*4*DD, ff2_b + (size_t)l*DMODEL, pproj,
            NTOK, DMODEL, DF);
        ln_kernel<<<NTOK, 256>>>(px, pproj, ln2_g + (size_t)l*DMODEL, ln2_b + (size_t)l*DMODEL, px, pxr);
    }

    int nblk = (out_size + 255) / 256;
    if (nblk > 0) copy_kernel<<<nblk, 256>>>(out, out_size);
}

// round 5
// speedup vs baseline: 5.9415x; 1.4598x over previous
#include <cuda_runtime.h>
#include <cuda_fp16.h>
#include <cstdint>

// Problem constants
#define LAYERS 6
#define BATCH  8
#define SEQ    1024
#define NTOK   (BATCH*SEQ)   // 8192
#define DMODEL 768
#define NHEAD  12
#define HDIM   64
#define D3     2304          // 3*DMODEL
#define DF     3072          // 4*DMODEL

#define DD     (DMODEL*DMODEL)
// half-precision weight scratch layout
#define OFF_QKV 0
#define OFF_OUT (LAYERS*3*DD)
#define OFF_FF1 (OFF_OUT + LAYERS*DD)
#define OFF_FF2 (OFF_FF1 + LAYERS*4*DD)
#define WTOTAL  (OFF_FF2 + LAYERS*4*DD)

// -------- scratch (device globals: no allocations allowed) --------
__device__ float  g_x   [NTOK*DMODEL];   // exact activations (residual path)
__device__ __half g_xh  [NTOK*DMODEL];   // half copy (GEMM A input)
__device__ float  g_qkv [NTOK*D3];       // qkv (attention reads fp32)
__device__ __half g_ah  [NTOK*DMODEL];   // attention context (half, out-proj A)
__device__ float  g_proj[NTOK*DMODEL];   // proj / ffn2 output (fp32 for residual)
__device__ __half g_hh  [NTOK*DF];       // ffn hidden (half, ff2 A)
__device__ __half g_wh  [WTOTAL];        // half weights
__device__ int    g_pos [NTOK];
__device__ int    g_pad [NTOK];

// ---------------- helpers ----------------
__device__ __forceinline__ uint32_t tf32u(float x) {
    uint32_t r;
    asm("cvt.rna.tf32.f32 %0, %1;" : "=r"(r) : "f"(x));
    return r;
}

__device__ __forceinline__ uint32_t smem_u32(const void* p) {
    uint32_t a;
    asm("{ .reg .u64 t; cvta.to.shared.u64 t, %1; cvt.u32.u64 %0, t; }" : "=r"(a) : "l"(p));
    return a;
}

__device__ __forceinline__ void cp16(uint32_t dst, const void* src) {
    asm volatile("cp.async.cg.shared.global [%0], [%1], 16;" :: "r"(dst), "l"(src));
}
#define CP_COMMIT() asm volatile("cp.async.commit_group;" ::: "memory")
#define CP_WAIT(n)  asm volatile("cp.async.wait_group %0;" :: "n"(n) : "memory")

// fp16 tensor-core mma: D(f32) += A(f16) * B(f16), 16x8x16
__device__ __forceinline__ void mma16(float d[4],
                                      uint32_t a0, uint32_t a1, uint32_t a2, uint32_t a3,
                                      uint32_t b0, uint32_t b1) {
    asm volatile(
        "mma.sync.aligned.m16n8k16.row.col.f32.f16.f16.f32 "
        "{%0,%1,%2,%3}, {%4,%5,%6,%7}, {%8,%9}, {%0,%1,%2,%3};\n"
        : "+f"(d[0]), "+f"(d[1]), "+f"(d[2]), "+f"(d[3])
        : "r"(a0), "r"(a1), "r"(a2), "r"(a3), "r"(b0), "r"(b1));
}

// tf32 mma (attention only)
__device__ __forceinline__ void mma8(float d[4],
                                     uint32_t a0, uint32_t a1, uint32_t a2, uint32_t a3,
                                     uint32_t b0, uint32_t b1) {
    asm volatile(
        "mma.sync.aligned.m16n8k8.row.col.f32.tf32.tf32.f32 "
        "{%0,%1,%2,%3}, {%4,%5,%6,%7}, {%8,%9}, {%0,%1,%2,%3};\n"
        : "+f"(d[0]), "+f"(d[1]), "+f"(d[2]), "+f"(d[3])
        : "r"(a0), "r"(a1), "r"(a2), "r"(a3), "r"(b0), "r"(b1));
}

// ---------------- one-time weight f32 -> f16 ----------------
__global__ void w2h_kernel(const float* __restrict__ src, __half* __restrict__ dst, int n4) {
    int i = blockIdx.x*256 + threadIdx.x;
    if (i >= n4) return;
    float4 v = ((const float4*)src)[i];
    __half2 h0 = __floats2half2_rn(v.x, v.y);
    __half2 h1 = __floats2half2_rn(v.z, v.w);
    ((__half2*)dst)[i*2]   = h0;
    ((__half2*)dst)[i*2+1] = h1;
}

// ---------------- positions + pad mask ----------------
__global__ void pos_kernel(const int* __restrict__ tokens) {
    __shared__ int s[SEQ];
    int b = blockIdx.x, i = threadIdx.x;
    int t = tokens[b*SEQ + i];
    int isp = (t == 0);
    g_pad[b*SEQ + i] = isp;
    s[i] = 1 - isp;
    __syncthreads();
    for (int off = 1; off < SEQ; off <<= 1) {
        int v = (i >= off) ? s[i - off] : 0;
        __syncthreads();
        if (i >= off) s[i] += v;
        __syncthreads();
    }
    g_pos[b*SEQ + i] = isp ? 0 : s[i];
}

// ---------------- embedding (writes exact f32 + half) ----------------
__global__ void embed_kernel(const int* __restrict__ tokens,
                             const float* __restrict__ tok_emb,
                             const float* __restrict__ pos_emb) {
    int n = blockIdx.x;
    int d = threadIdx.x * 4;
    int t = tokens[n];
    int p = g_pos[n];
    float4 a = *(const float4*)&tok_emb[(size_t)t*DMODEL + d];
    float4 c = *(const float4*)&pos_emb[(size_t)p*DMODEL + d];
    a.x += c.x; a.y += c.y; a.z += c.z; a.w += c.w;
    *(float4*)&g_x[(size_t)n*DMODEL + d] = a;
    __half2 h0 = __floats2half2_rn(a.x, a.y);
    __half2 h1 = __floats2half2_rn(a.z, a.w);
    *(__half2*)&g_xh[(size_t)n*DMODEL + d]     = h0;
    *(__half2*)&g_xh[(size_t)n*DMODEL + d + 2] = h1;
}

// ---------------- GELU ----------------
__device__ __forceinline__ float gelu_f(float x) {
    float x3 = x*x*x;
    return 0.5f*x*(1.f + tanhf(0.7978845608028654f*(x + 0.044715f*x3)));
}

// ================= GEMM v3: fp16 m16n8k16 + cp.async double buffer =================
// C[M,N] = A[M,K]*B[N,K]^T + bias. 128x128x32 tile, 256 thr = 8 warps (2m x 4n),
// warp tile 64x32 = 4x4 m16n8k16 atoms. smem half [128][40] -> conflict-free.
#define PADH   40
#define HSTAGE (128*PADH)     // halfs per operand per stage (10240 B)

template<bool GELU, bool OUTH>
__global__ void __launch_bounds__(256) gemmh(const __half* __restrict__ A,
                                             const __half* __restrict__ B,
                                             const float* __restrict__ bias,
                                             void* __restrict__ Cv,
                                             int M, int N, int K) {
    __shared__ __half sm[4*HSTAGE];   // A0,A1,B0,B1 = 40960 B
    __half* As = sm;
    __half* Bs = sm + 2*HSTAGE;
    uint32_t aAddr = smem_u32(As), bAddr = smem_u32(Bs);

    int tid = threadIdx.x, warp = tid >> 5, lane = tid & 31;
    int g = lane >> 2, c = lane & 3;
    int wm = (warp & 1) * 64, wn = (warp >> 1) * 32;
    int bm = blockIdx.y * 128, bn = blockIdx.x * 128;

    const __half* Ag = A + (size_t)bm * K;
    const __half* Bg = B + (size_t)bn * K;
    int nkt = K >> 5;

    float acc[4][4][4];
#pragma unroll
    for (int i = 0; i < 4; i++)
#pragma unroll
        for (int j = 0; j < 4; j++)
#pragma unroll
            for (int r = 0; r < 4; r++) acc[i][j][r] = 0.f;

    auto issue = [&](int kt) {
        int st = kt & 1;
        int k0 = kt << 5;
        uint32_t aB = aAddr + st * (HSTAGE*2);
        uint32_t bB = bAddr + st * (HSTAGE*2);
#pragma unroll
        for (int p = 0; p < 2; p++) {
            int ci = p*256 + tid;
            int r = ci >> 2, kc = ci & 3;          // 16B chunk = 8 halfs
            cp16(aB + (uint32_t)(r*80 + kc*16), Ag + (size_t)r*K + k0 + kc*8);
            cp16(bB + (uint32_t)(r*80 + kc*16), Bg + (size_t)r*K + k0 + kc*8);
        }
        CP_COMMIT();
    };

    issue(0);
    for (int kt = 0; kt < nkt; kt++) {
        int st = kt & 1;
        if (kt + 1 < nkt) { issue(kt + 1); CP_WAIT(1); }
        else              { CP_WAIT(0); }
        __syncthreads();

        const __half* Ast = As + st*HSTAGE;
        const __half* Bst = Bs + st*HSTAGE;
#pragma unroll
        for (int ks = 0; ks < 2; ks++) {
            int kb = ks*16;
            uint32_t af[4][4], bf[4][2];
#pragma unroll
            for (int i = 0; i < 4; i++) {
                int rr = wm + i*16 + g;
                af[i][0] = *(const uint32_t*)&Ast[rr*PADH     + kb + 2*c];
                af[i][1] = *(const uint32_t*)&Ast[(rr+8)*PADH + kb + 2*c];
                af[i][2] = *(const uint32_t*)&Ast[rr*PADH     + kb + 2*c + 8];
                af[i][3] = *(const uint32_t*)&Ast[(rr+8)*PADH + kb + 2*c + 8];
            }
#pragma unroll
            for (int j = 0; j < 4; j++) {
                int col = wn + j*8 + g;
                bf[j][0] = *(const uint32_t*)&Bst[col*PADH + kb + 2*c];
                bf[j][1] = *(const uint32_t*)&Bst[col*PADH + kb + 2*c + 8];
            }
#pragma unroll
            for (int i = 0; i < 4; i++)
#pragma unroll
                for (int j = 0; j < 4; j++)
                    mma16(acc[i][j], af[i][0], af[i][1], af[i][2], af[i][3], bf[j][0], bf[j][1]);
        }
        __syncthreads();
    }

    // epilogue: bias (+gelu), store f32 or f16
#pragma unroll
    for (int j = 0; j < 4; j++) {
        int col0 = bn + wn + j*8 + c*2;
        float b0 = bias[col0], b1 = bias[col0 + 1];
#pragma unroll
        for (int i = 0; i < 4; i++) {
            int rr = bm + wm + i*16 + g;
            float v00 = acc[i][j][0] + b0, v01 = acc[i][j][1] + b1;
            float v10 = acc[i][j][2] + b0, v11 = acc[i][j][3] + b1;
            if (GELU) { v00 = gelu_f(v00); v01 = gelu_f(v01); v10 = gelu_f(v10); v11 = gelu_f(v11); }
            if (OUTH) {
                __half* C = (__half*)Cv;
                *(__half2*)&C[(size_t)rr * N + col0]       = __floats2half2_rn(v00, v01);
                *(__half2*)&C[(size_t)(rr + 8) * N + col0] = __floats2half2_rn(v10, v11);
            } else {
                float* C = (float*)Cv;
                *(float2*)&C[(size_t)rr * N + col0]       = make_float2(v00, v01);
                *(float2*)&C[(size_t)(rr + 8) * N + col0] = make_float2(v10, v11);
            }
        }
    }
}

// ---------------- attention: flash-style with tf32 mma, half output ----------------
__global__ void __launch_bounds__(128) attn_mma(const float* __restrict__ qkv,
                                                __half* __restrict__ out) {
    __shared__ float sK[64][68];
    __shared__ float sV[64][72];

    int b = blockIdx.z, h = blockIdx.y, qb = blockIdx.x;
    int tid = threadIdx.x, warp = tid >> 5, lane = tid & 31;
    int g = lane >> 2, c = lane & 3;
    int q0 = qb * 64;
    const int* padp = &g_pad[b*SEQ];

    uint32_t qa[8][4];
    int qg0 = q0 + warp*16 + g, qg1 = qg0 + 8;
    {
        const float* Q0 = qkv + (size_t)(b*SEQ + qg0) * D3 + h*HDIM;
        const float* Q1 = qkv + (size_t)(b*SEQ + qg1) * D3 + h*HDIM;
#pragma unroll
        for (int ks = 0; ks < 8; ks++) {
            qa[ks][0] = tf32u(Q0[ks*8 + c]     * 0.125f);
            qa[ks][1] = tf32u(Q1[ks*8 + c]     * 0.125f);
            qa[ks][2] = tf32u(Q0[ks*8 + c + 4] * 0.125f);
            qa[ks][3] = tf32u(Q1[ks*8 + c + 4] * 0.125f);
        }
    }

    float m0 = -1e30f, m1 = -1e30f, l0 = 0.f, l1 = 0.f;
    float o[8][4];
#pragma unroll
    for (int na = 0; na < 8; na++)
#pragma unroll
        for (int r = 0; r < 4; r++) o[na][r] = 0.f;

    int nch = q0/64 + 1;
    for (int ch = 0; ch < nch; ch++) {
        __syncthreads();
#pragma unroll
        for (int p = 0; p < 8; p++) {
            int idx = tid + p*128;
            int r = idx >> 4, q4 = (idx & 15) << 2;
            const float* base = qkv + (size_t)(b*SEQ + ch*64 + r) * D3 + h*HDIM;
            float4 kv = *(const float4*)(base + DMODEL   + q4);
            float4 vv = *(const float4*)(base + 2*DMODEL + q4);
            sK[r][q4+0] = kv.x; sK[r][q4+1] = kv.y;
            sK[r][q4+2] = kv.z; sK[r][q4+3] = kv.w;
            sV[r][q4+0] = vv.x; sV[r][q4+1] = vv.y;
            sV[r][q4+2] = vv.z; sV[r][q4+3] = vv.w;
        }
        __syncthreads();

        float s[8][4];
#pragma unroll
        for (int na = 0; na < 8; na++)
#pragma unroll
            for (int r = 0; r < 4; r++) s[na][r] = 0.f;
#pragma unroll
        for (int ks = 0; ks < 8; ks++) {
#pragma unroll
            for (int na = 0; na < 8; na++) {
                uint32_t b0 = __float_as_uint(sK[na*8 + g][ks*8 + c]);
                uint32_t b1 = __float_as_uint(sK[na*8 + g][ks*8 + c + 4]);
                mma8(s[na], qa[ks][0], qa[ks][1], qa[ks][2], qa[ks][3], b0, b1);
            }
        }

        float mc0 = -1e30f, mc1 = -1e30f;
#pragma unroll
        for (int na = 0; na < 8; na++) {
            int j = ch*64 + na*8 + c*2;
            int p0 = padp[j], p1 = padp[j+1];
            float v00 = (j   > qg0 || p0) ? -1e9f : s[na][0];
            float v01 = (j+1 > qg0 || p1) ? -1e9f : s[na][1];
            float v10 = (j   > qg1 || p0) ? -1e9f : s[na][2];
            float v11 = (j+1 > qg1 || p1) ? -1e9f : s[na][3];
            s[na][0] = v00; s[na][1] = v01; s[na][2] = v10; s[na][3] = v11;
            mc0 = fmaxf(mc0, fmaxf(v00, v01));
            mc1 = fmaxf(mc1, fmaxf(v10, v11));
        }
        mc0 = fmaxf(mc0, __shfl_xor_sync(0xffffffffu, mc0, 1));
        mc0 = fmaxf(mc0, __shfl_xor_sync(0xffffffffu, mc0, 2));
        mc1 = fmaxf(mc1, __shfl_xor_sync(0xffffffffu, mc1, 1));
        mc1 = fmaxf(mc1, __shfl_xor_sync(0xffffffffu, mc1, 2));
        float mn0 = fmaxf(m0, mc0), mn1 = fmaxf(m1, mc1);
        float al0 = __expf(m0 - mn0), al1 = __expf(m1 - mn1);
        m0 = mn0; m1 = mn1;

        float ps0 = 0.f, ps1 = 0.f;
#pragma unroll
        for (int na = 0; na < 8; na++) {
            s[na][0] = __expf(s[na][0] - mn0);
            s[na][1] = __expf(s[na][1] - mn0);
            s[na][2] = __expf(s[na][2] - mn1);
            s[na][3] = __expf(s[na][3] - mn1);
            ps0 += s[na][0] + s[na][1];
            ps1 += s[na][2] + s[na][3];
        }
        ps0 += __shfl_xor_sync(0xffffffffu, ps0, 1);
        ps0 += __shfl_xor_sync(0xffffffffu, ps0, 2);
        ps1 += __shfl_xor_sync(0xffffffffu, ps1, 1);
        ps1 += __shfl_xor_sync(0xffffffffu, ps1, 2);
        l0 = l0 * al0 + ps0;
        l1 = l1 * al1 + ps1;
#pragma unroll
        for (int na = 0; na < 8; na++) {
            o[na][0] *= al0; o[na][1] *= al0;
            o[na][2] *= al1; o[na][3] *= al1;
        }

        int srcA = (g << 2) + (c >> 1), srcB = srcA + 2;
        int sel = c & 1;
#pragma unroll
        for (int kk = 0; kk < 8; kk++) {
            float pa0 = __shfl_sync(0xffffffffu, s[kk][0], srcA);
            float pa1 = __shfl_sync(0xffffffffu, s[kk][1], srcA);
            float pa2 = __shfl_sync(0xffffffffu, s[kk][2], srcA);
            float pa3 = __shfl_sync(0xffffffffu, s[kk][3], srcA);
            float pb0 = __shfl_sync(0xffffffffu, s[kk][0], srcB);
            float pb1 = __shfl_sync(0xffffffffu, s[kk][1], srcB);
            float pb2 = __shfl_sync(0xffffffffu, s[kk][2], srcB);
            float pb3 = __shfl_sync(0xffffffffu, s[kk][3], srcB);
            uint32_t a0 = tf32u(sel ? pa1 : pa0);
            uint32_t a1 = tf32u(sel ? pa3 : pa2);
            uint32_t a2 = tf32u(sel ? pb1 : pb0);
            uint32_t a3 = tf32u(sel ? pb3 : pb2);
#pragma unroll
            for (int na = 0; na < 8; na++) {
                uint32_t b0 = __float_as_uint(sV[kk*8 + c    ][na*8 + g]);
                uint32_t b1 = __float_as_uint(sV[kk*8 + c + 4][na*8 + g]);
                mma8(o[na], a0, a1, a2, a3, b0, b1);
            }
        }
    }

    // normalize, write half (feeds out-proj GEMM)
    float inv0 = (m0 > -1e8f) ? 1.f / l0 : 0.f;
    float inv1 = (m1 > -1e8f) ? 1.f / l1 : 0.f;
    __half* O0 = out + (size_t)(b*SEQ + qg0) * DMODEL + h*HDIM;
    __half* O1 = out + (size_t)(b*SEQ + qg1) * DMODEL + h*HDIM;
#pragma unroll
    for (int na = 0; na < 8; na++) {
        int col = na*8 + c*2;
        *(__half2*)&O0[col] = __floats2half2_rn(o[na][0]*inv0, o[na][1]*inv0);
        *(__half2*)&O1[col] = __floats2half2_rn(o[na][2]*inv1, o[na][3]*inv1);
    }
}

// ---------------- layernorm(x + add), writes exact f32 + half ----------------
__device__ __forceinline__ float block_sum(float v, float* sh) {
    int lane = threadIdx.x & 31, w = threadIdx.x >> 5;
#pragma unroll
    for (int o = 16; o; o >>= 1) v += __shfl_xor_sync(0xffffffffu, v, o);
    if (lane == 0) sh[w] = v;
    __syncthreads();
    float r = 0.f;
#pragma unroll
    for (int i = 0; i < 8; i++) r += sh[i];
    __syncthreads();
    return r;
}

__global__ void __launch_bounds__(256) ln_kernel(const float* __restrict__ xin,
                                                 const float* __restrict__ add,
                                                 const float* __restrict__ g,
                                                 const float* __restrict__ bta,
                                                 float* __restrict__ xout,
                                                 __half* __restrict__ xouth) {
    __shared__ float sh[8];
    int n = blockIdx.x, tid = threadIdx.x;
    float v[3];
    float s = 0.f;
#pragma unroll
    for (int i = 0; i < 3; i++) {
        int d = tid + i*256;
        v[i] = xin[(size_t)n*DMODEL + d] + add[(size_t)n*DMODEL + d];
        s += v[i];
    }
    s = block_sum(s, sh);
    float mu = s * (1.f/768.f);
    float q = 0.f;
#pragma unroll
    for (int i = 0; i < 3; i++) { float dv = v[i] - mu; q += dv*dv; }
    q = block_sum(q, sh);
    float rstd = rsqrtf(q * (1.f/768.f) + 1e-5f);
#pragma unroll
    for (int i = 0; i < 3; i++) {
        int d = tid + i*256;
        float o = (v[i] - mu) * rstd * g[d] + bta[d];
        xout [(size_t)n*DMODEL + d] = o;
        xouth[(size_t)n*DMODEL + d] = __float2half_rn(o);
    }
}

// ---------------- output copy ----------------
__global__ void copy_kernel(float* __restrict__ out, int out_size) {
    int idx = blockIdx.x*256 + threadIdx.x;
    if (idx >= out_size) return;
    const int NX = NTOK*DMODEL;
    if (idx < NX) {
        out[idx] = g_x[idx];
    } else {
        int pi = idx - NX;
        out[idx] = (pi < NTOK && g_pad[pi]) ? 1.f : 0.f;
    }
}

// ---------------- launcher ----------------
extern "C" void kernel_launch(void* const* d_in, const int* in_sizes, int n_in,
                              void* d_out, int out_size) {
    const int*   tokens  = (const int*)  d_in[0];
    const float* tok_emb = (const float*)d_in[1];
    const float* pos_emb = (const float*)d_in[2];
    const float* qkv_w   = (const float*)d_in[3];
    const float* qkv_b   = (const float*)d_in[4];
    const float* out_w   = (const float*)d_in[5];
    const float* out_b   = (const float*)d_in[6];
    const float* ln1_g   = (const float*)d_in[7];
    const float* ln1_b   = (const float*)d_in[8];
    const float* ff1_w   = (const float*)d_in[9];
    const float* ff1_b   = (const float*)d_in[10];
    const float* ff2_w   = (const float*)d_in[11];
    const float* ff2_b   = (const float*)d_in[12];
    const float* ln2_g   = (const float*)d_in[13];
    const float* ln2_b   = (const float*)d_in[14];
    float* out = (float*)d_out;

    float *px, *pqkv, *pproj;
    __half *pxh, *pah, *phh, *pwh;
    cudaGetSymbolAddress((void**)&px,    g_x);
    cudaGetSymbolAddress((void**)&pxh,   g_xh);
    cudaGetSymbolAddress((void**)&pqkv,  g_qkv);
    cudaGetSymbolAddress((void**)&pah,   g_ah);
    cudaGetSymbolAddress((void**)&pproj, g_proj);
    cudaGetSymbolAddress((void**)&phh,   g_hh);
    cudaGetSymbolAddress((void**)&pwh,   g_wh);

    // one-time weight conversion to half
    w2h_kernel<<<(LAYERS*3*DD/4 + 255)/256, 256>>>(qkv_w, pwh + OFF_QKV, LAYERS*3*DD/4);
    w2h_kernel<<<(LAYERS*DD/4   + 255)/256, 256>>>(out_w, pwh + OFF_OUT, LAYERS*DD/4);
    w2h_kernel<<<(LAYERS*4*DD/4 + 255)/256, 256>>>(ff1_w, pwh + OFF_FF1, LAYERS*4*DD/4);
    w2h_kernel<<<(LAYERS*4*DD/4 + 255)/256, 256>>>(ff2_w, pwh + OFF_FF2, LAYERS*4*DD/4);

    pos_kernel<<<BATCH, SEQ>>>(tokens);
    embed_kernel<<<NTOK, DMODEL/4>>>(tokens, tok_emb, pos_emb);

    for (int l = 0; l < LAYERS; l++) {
        gemmh<false,false><<<dim3(D3/128, NTOK/128), 256>>>(
            pxh, pwh + OFF_QKV + (size_t)l*3*DD, qkv_b + (size_t)l*D3, pqkv,
            NTOK, D3, DMODEL);
        attn_mma<<<dim3(SEQ/64, NHEAD, BATCH), 128>>>(pqkv, pah);
        gemmh<false,false><<<dim3(DMODEL/128, NTOK/128), 256>>>(
            pah, pwh + OFF_OUT + (size_t)l*DD, out_b + (size_t)l*DMODEL, pproj,
            NTOK, DMODEL, DMODEL);
        ln_kernel<<<NTOK, 256>>>(px, pproj, ln1_g + (size_t)l*DMODEL, ln1_b + (size_t)l*DMODEL, px, pxh);
        gemmh<true,true><<<dim3(DF/128, NTOK/128), 256>>>(
            pxh, pwh + OFF_FF1 + (size_t)l*4*DD, ff1_b + (size_t)l*DF, phh,
            NTOK, DF, DMODEL);
        gemmh<false,false><<<dim3(DMODEL/128, NTOK/128), 256>>>(
            phh, pwh + OFF_FF2 + (size_t)l*4*DD, ff2_b + (size_t)l*DMODEL, pproj,
            NTOK, DMODEL, DF);
        ln_kernel<<<NTOK, 256>>>(px, pproj, ln2_g + (size_t)l*DMODEL, ln2_b + (size_t)l*DMODEL, px, pxh);
    }

    int nblk = (out_size + 255) / 256;
    if (nblk > 0) copy_kernel<<<nblk, 256>>>(out, out_size);
}